// round 1
// baseline (speedup 1.0000x reference)
#include <cuda_runtime.h>
#include <math.h>

#define BATCH 4
#define CH 512
#define HW 16384   // 128*128
#define KC 32
#define EPSV 1e-5f

// ---------------- scratch (device globals; no allocations allowed) ----------
__device__ float g_z[(size_t)BATCH * CH * HW];     // 134 MB: conv+BN+ReLU output, [b][c][n]
__device__ float g_agg[BATCH * KC * CH];           // sum_n assign*z
__device__ float g_asum[BATCH * KC];               // sum_n assign
__device__ float g_feat[BATCH * CH];
__device__ float g_gamma[BATCH * CH];

// ---------------- zero accumulators (must re-zero on every graph replay) ----
__global__ void zero_kernel() {
    int i = blockIdx.x * blockDim.x + threadIdx.x;
    if (i < BATCH * KC * CH) g_agg[i] = 0.f;
    if (i < BATCH * KC)      g_asum[i] = 0.f;
}

// ---------------- K1: SGEMM (conv 1x1) + BN2 + ReLU ------------------------
// z[b][o][n] = relu( (sum_c w[o][c] * x[b][c][n]) * alpha[o] + beta[o] )
__global__ __launch_bounds__(256) void gemm_bn_relu(
    const float* __restrict__ x, const float* __restrict__ w,
    const float* __restrict__ bn_g, const float* __restrict__ bn_b,
    const float* __restrict__ bn_m, const float* __restrict__ bn_v)
{
    __shared__ float As[8][128];   // A tile transposed: [k][m]
    __shared__ float Bs[8][128];   // B tile: [k][n]
    const int b  = blockIdx.z;
    const int m0 = blockIdx.y * 128;
    const int n0 = blockIdx.x * 128;
    const float* xb = x   + (size_t)b * CH * HW;
    float*       zb = g_z + (size_t)b * CH * HW;
    const int tid = threadIdx.x;
    const int tx = tid & 15, ty = tid >> 4;

    float acc[8][8];
    #pragma unroll
    for (int i = 0; i < 8; i++)
        #pragma unroll
        for (int j = 0; j < 8; j++) acc[i][j] = 0.f;

    const int arow = tid >> 1, acol = (tid & 1) * 4;
    const int brow = tid >> 5, bcol = (tid & 31) * 4;

    for (int k0 = 0; k0 < CH; k0 += 8) {
        float4 av = *(const float4*)&w[(size_t)(m0 + arow) * CH + k0 + acol];
        As[acol + 0][arow] = av.x;
        As[acol + 1][arow] = av.y;
        As[acol + 2][arow] = av.z;
        As[acol + 3][arow] = av.w;
        *(float4*)&Bs[brow][bcol] =
            *(const float4*)&xb[(size_t)(k0 + brow) * HW + n0 + bcol];
        __syncthreads();
        #pragma unroll
        for (int kk = 0; kk < 8; kk++) {
            float a[8], bb[8];
            *(float4*)&a[0]  = *(float4*)&As[kk][ty * 4];
            *(float4*)&a[4]  = *(float4*)&As[kk][64 + ty * 4];
            *(float4*)&bb[0] = *(float4*)&Bs[kk][tx * 4];
            *(float4*)&bb[4] = *(float4*)&Bs[kk][64 + tx * 4];
            #pragma unroll
            for (int i = 0; i < 8; i++)
                #pragma unroll
                for (int j = 0; j < 8; j++) acc[i][j] += a[i] * bb[j];
        }
        __syncthreads();
    }

    #pragma unroll
    for (int i = 0; i < 8; i++) {
        const int ml = (i < 4) ? (ty * 4 + i) : (64 + ty * 4 + (i - 4));
        const int mm = m0 + ml;
        const float al = bn_g[mm] * rsqrtf(bn_v[mm] + EPSV);
        const float be = bn_b[mm] - bn_m[mm] * al;
        float4 o0, o1;
        o0.x = fmaxf(acc[i][0] * al + be, 0.f);
        o0.y = fmaxf(acc[i][1] * al + be, 0.f);
        o0.z = fmaxf(acc[i][2] * al + be, 0.f);
        o0.w = fmaxf(acc[i][3] * al + be, 0.f);
        o1.x = fmaxf(acc[i][4] * al + be, 0.f);
        o1.y = fmaxf(acc[i][5] * al + be, 0.f);
        o1.z = fmaxf(acc[i][6] * al + be, 0.f);
        o1.w = fmaxf(acc[i][7] * al + be, 0.f);
        *(float4*)&zb[(size_t)mm * HW + n0 + tx * 4]      = o0;
        *(float4*)&zb[(size_t)mm * HW + n0 + 64 + tx * 4] = o1;
    }
}

// ---------------- K3: encoding (softmax assign + aggregation) ---------------
// One block = 256 pixels of one batch. Pass A: per-thread xc[k], x2, softmax.
// Pass B: block-local GEMM agg[k][c] += sum_n assign[n][k]*z[n][c], atomic flush.
__global__ __launch_bounds__(256) void encode_kernel(
    const float* __restrict__ codewords, const float* __restrict__ scale)
{
    extern __shared__ float sm[];
    float* cwT  = sm;                    // [c][k]  CH*KC = 16384 floats
    float* a_s  = cwT + CH * KC;         // [n][k] stride 33 -> 256*33 = 8448
    float* z_s  = a_s + 256 * 33;        // [64][256] = 16384
    float* sc_s = z_s + 64 * 256;        // 32
    float* c2_s = sc_s + 32;             // 32

    const int tid = threadIdx.x;
    const int b   = blockIdx.y;
    const int n0  = blockIdx.x * 256;
    const float* zb = g_z + (size_t)b * CH * HW;

    // stage codewords transposed: cwT[c*32+k] = codewords[k*512+c]
    for (int i = tid; i < CH * KC; i += 256) {
        int k = i >> 9;      // /512
        int c = i & 511;
        cwT[c * KC + k] = codewords[i];
    }
    __syncthreads();
    if (tid < KC) {
        float s = 0.f;
        for (int c = 0; c < CH; c++) { float wv = cwT[c * KC + tid]; s += wv * wv; }
        c2_s[tid] = s;
        sc_s[tid] = scale[tid];
    }
    __syncthreads();

    // ---- pass A: xc, x2, softmax (each thread owns one pixel) ----
    const int n = n0 + tid;
    float x2 = 0.f;
    float xc[KC];
    #pragma unroll
    for (int k = 0; k < KC; k++) xc[k] = 0.f;
    for (int c = 0; c < CH; c++) {
        float vz = zb[(size_t)c * HW + n];
        x2 += vz * vz;
        const float4* wp = (const float4*)(cwT + c * KC);
        #pragma unroll
        for (int k4 = 0; k4 < 8; k4++) {
            float4 wv = wp[k4];
            xc[k4 * 4 + 0] += vz * wv.x;
            xc[k4 * 4 + 1] += vz * wv.y;
            xc[k4 * 4 + 2] += vz * wv.z;
            xc[k4 * 4 + 3] += vz * wv.w;
        }
    }
    float mx = -1e30f;
    #pragma unroll
    for (int k = 0; k < KC; k++) {
        float s = sc_s[k] * (x2 - 2.f * xc[k] + c2_s[k]);
        xc[k] = s;
        mx = fmaxf(mx, s);
    }
    float ssum = 0.f;
    #pragma unroll
    for (int k = 0; k < KC; k++) { float e = __expf(xc[k] - mx); xc[k] = e; ssum += e; }
    float inv = 1.f / ssum;
    #pragma unroll
    for (int k = 0; k < KC; k++) a_s[tid * 33 + k] = xc[k] * inv;
    __syncthreads();

    if (tid < KC) {
        float s = 0.f;
        for (int nn = 0; nn < 256; nn++) s += a_s[nn * 33 + tid];
        atomicAdd(&g_asum[b * KC + tid], s);
    }

    // ---- pass B: agg GEMM over c-chunks of 64 ----
    const int k  = tid & 31;
    const int cg = tid >> 5;   // warp id 0..7 -> owns 8 channels per chunk
    for (int c0 = 0; c0 < CH; c0 += 64) {
        __syncthreads();
        #pragma unroll
        for (int i = 0; i < 16; i++) {
            int f4  = tid + i * 256;
            int row = f4 >> 6;
            int col = (f4 & 63) * 4;
            *(float4*)&z_s[row * 256 + col] =
                *(const float4*)&zb[(size_t)(c0 + row) * HW + n0 + col];
        }
        __syncthreads();
        float accv[8];
        #pragma unroll
        for (int j = 0; j < 8; j++) accv[j] = 0.f;
        for (int nn = 0; nn < 256; nn++) {
            float a = a_s[nn * 33 + k];                 // conflict-free (stride 33)
            #pragma unroll
            for (int j = 0; j < 8; j++)
                accv[j] += a * z_s[(cg * 8 + j) * 256 + nn];  // warp broadcast
        }
        #pragma unroll
        for (int j = 0; j < 8; j++)
            atomicAdd(&g_agg[(b * KC + k) * CH + c0 + cg * 8 + j], accv[j]);
    }
}

// ---------------- K4: agg -> BN1 -> ReLU -> mean over codes -> feat ---------
__global__ void finalize_kernel(
    const float* __restrict__ codewords,
    const float* __restrict__ g1, const float* __restrict__ b1,
    const float* __restrict__ m1, const float* __restrict__ v1,
    float* __restrict__ dout)
{
    const int b = blockIdx.x, c = threadIdx.x;
    float acc = 0.f;
    #pragma unroll
    for (int k = 0; k < KC; k++) {
        float e = g_agg[(b * KC + k) * CH + c] - g_asum[b * KC + k] * codewords[k * CH + c];
        float al = g1[k] * rsqrtf(v1[k] + EPSV);
        e = (e - m1[k]) * al + b1[k];
        acc += fmaxf(e, 0.f);
    }
    float f = acc * (1.f / KC);
    g_feat[b * CH + c] = f;
    dout[b * CH + c] = f;          // output 0: feat [B, C]
}

// ---------------- K5: gamma = sigmoid(feat @ fc_w^T + fc_b) -----------------
__global__ void gamma_kernel(const float* __restrict__ fc_w, const float* __restrict__ fc_b)
{
    __shared__ float fs[CH];
    const int b = blockIdx.x, o = threadIdx.x;
    fs[o] = g_feat[b * CH + o];
    __syncthreads();
    float acc = fc_b[o];
    for (int c = 0; c < CH; c++) acc += fs[c] * fc_w[(size_t)o * CH + c];
    g_gamma[b * CH + o] = 1.f / (1.f + expf(-acc));
}

// ---------------- K6: out = relu(x * (1 + gamma)) ---------------------------
__global__ void out_kernel(const float* __restrict__ x, float* __restrict__ dout)
{
    const int i4 = blockIdx.x * blockDim.x + threadIdx.x;  // float4 index
    const int bc = i4 >> 12;                               // (i4*4)/16384
    const float gmm = 1.f + g_gamma[bc];
    float4 v = ((const float4*)x)[i4];
    float4 o;
    o.x = fmaxf(v.x * gmm, 0.f);
    o.y = fmaxf(v.y * gmm, 0.f);
    o.z = fmaxf(v.z * gmm, 0.f);
    o.w = fmaxf(v.w * gmm, 0.f);
    ((float4*)(dout + BATCH * CH))[i4] = o;                // output 1: out [B,C,H,W]
}

// ---------------- launcher --------------------------------------------------
extern "C" void kernel_launch(void* const* d_in, const int* in_sizes, int n_in,
                              void* d_out, int out_size)
{
    const float* x         = (const float*)d_in[0];
    const float* conv_w    = (const float*)d_in[1];
    const float* bn2_g     = (const float*)d_in[2];
    const float* bn2_b     = (const float*)d_in[3];
    const float* bn2_m     = (const float*)d_in[4];
    const float* bn2_v     = (const float*)d_in[5];
    const float* codewords = (const float*)d_in[6];
    const float* scale     = (const float*)d_in[7];
    const float* bn1_g     = (const float*)d_in[8];
    const float* bn1_b     = (const float*)d_in[9];
    const float* bn1_m     = (const float*)d_in[10];
    const float* bn1_v     = (const float*)d_in[11];
    const float* fc_w      = (const float*)d_in[12];
    const float* fc_b      = (const float*)d_in[13];
    float* dout = (float*)d_out;

    const size_t ENC_SMEM = (size_t)(CH * KC + 256 * 33 + 64 * 256 + 64) * sizeof(float);
    cudaFuncSetAttribute(encode_kernel, cudaFuncAttributeMaxDynamicSharedMemorySize,
                         (int)ENC_SMEM);

    gemm_bn_relu<<<dim3(HW / 128, CH / 128, BATCH), 256>>>(
        x, conv_w, bn2_g, bn2_b, bn2_m, bn2_v);
    zero_kernel<<<(BATCH * KC * CH + 255) / 256, 256>>>();
    encode_kernel<<<dim3(HW / 256, BATCH), 256, ENC_SMEM>>>(codewords, scale);
    finalize_kernel<<<BATCH, CH>>>(codewords, bn1_g, bn1_b, bn1_m, bn1_v, dout);
    gamma_kernel<<<BATCH, CH>>>(fc_w, fc_b);
    out_kernel<<<(BATCH * CH * HW / 4) / 256, 256>>>(x, dout);
}

// round 11
// speedup vs baseline: 1.2668x; 1.2668x over previous
#include <cuda_runtime.h>
#include <math.h>
#include <stdint.h>

#define BATCH 4
#define CH 512
#define HW 16384   // 128*128
#define KC 32
#define EPSV 1e-5f

// ---------------- scratch (device globals; no allocations allowed) ----------
__device__ float g_z[(size_t)BATCH * CH * HW];     // 134 MB: conv+BN+ReLU output, [b][c][n]
__device__ float g_agg[BATCH * KC * CH];           // sum_n assign*z
__device__ float g_asum[BATCH * KC];               // sum_n assign
__device__ float g_feat[BATCH * CH];
__device__ float g_gamma[BATCH * CH];

// ---------------- f32x2 helpers (packed dual-FMA; sm_100-family PTX) --------
// fma.rn.f32x2 is a family feature (PTX ISA 8.6, sm_100+), NOT an 'a'-suffix
// accelerated feature -> assembles under the harness's plain sm_103 target.
__device__ __forceinline__ uint64_t dup_f32(float v) {
    uint64_t d; asm("mov.b64 %0, {%1, %1};" : "=l"(d) : "f"(v)); return d;
}
__device__ __forceinline__ uint64_t pack_f32(float lo, float hi) {
    uint64_t d; asm("mov.b64 %0, {%1, %2};" : "=l"(d) : "f"(lo), "f"(hi)); return d;
}
__device__ __forceinline__ void unpack_f32(uint64_t v, float& lo, float& hi) {
    asm("mov.b64 {%0, %1}, %2;" : "=f"(lo), "=f"(hi) : "l"(v));
}
#define FMA2(acc, a, b) \
    asm("fma.rn.f32x2 %0, %1, %2, %0;" : "+l"(acc) : "l"(a), "l"(b))

// ---------------- zero accumulators (must re-zero on every graph replay) ----
__global__ void zero_kernel() {
    int i = blockIdx.x * blockDim.x + threadIdx.x;
    if (i < BATCH * KC * CH) g_agg[i] = 0.f;
    if (i < BATCH * KC)      g_asum[i] = 0.f;
}

// ---------------- K1: SGEMM (conv 1x1) + BN2 + ReLU, FFMA2 inner loop ------
// z[b][o][n] = relu( (sum_c w[o][c] * x[b][c][n]) * alpha[o] + beta[o] )
__global__ __launch_bounds__(256, 2) void gemm_bn_relu(
    const float* __restrict__ x, const float* __restrict__ w,
    const float* __restrict__ bn_g, const float* __restrict__ bn_b,
    const float* __restrict__ bn_m, const float* __restrict__ bn_v)
{
    __shared__ float As[8][128];   // A tile transposed: [k][m]
    __shared__ float Bs[8][128];   // B tile: [k][n]
    const int b  = blockIdx.z;
    const int m0 = blockIdx.y * 128;
    const int n0 = blockIdx.x * 128;
    const float* xb = x   + (size_t)b * CH * HW;
    float*       zb = g_z + (size_t)b * CH * HW;
    const int tid = threadIdx.x;
    const int tx = tid & 15, ty = tid >> 4;

    // packed accumulators: 8 m-rows x 4 n-col-pairs (cols tx*4+0..3, 64+tx*4+0..3)
    uint64_t acc2[8][4];
    #pragma unroll
    for (int i = 0; i < 8; i++)
        #pragma unroll
        for (int j = 0; j < 4; j++) acc2[i][j] = 0ull;

    const int arow = tid >> 1, acol = (tid & 1) * 4;
    const int brow = tid >> 5, bcol = (tid & 31) * 4;

    for (int k0 = 0; k0 < CH; k0 += 8) {
        float4 av = *(const float4*)&w[(size_t)(m0 + arow) * CH + k0 + acol];
        As[acol + 0][arow] = av.x;
        As[acol + 1][arow] = av.y;
        As[acol + 2][arow] = av.z;
        As[acol + 3][arow] = av.w;
        *(float4*)&Bs[brow][bcol] =
            *(const float4*)&xb[(size_t)(k0 + brow) * HW + n0 + bcol];
        __syncthreads();
        #pragma unroll
        for (int kk = 0; kk < 8; kk++) {
            float a[8];
            *(float4*)&a[0] = *(float4*)&As[kk][ty * 4];
            *(float4*)&a[4] = *(float4*)&As[kk][64 + ty * 4];
            uint64_t ad[8];
            #pragma unroll
            for (int i = 0; i < 8; i++) ad[i] = dup_f32(a[i]);
            double2 t0 = *(const double2*)&Bs[kk][tx * 4];        // 16B-aligned
            double2 t1 = *(const double2*)&Bs[kk][64 + tx * 4];
            uint64_t b2[4];
            b2[0] = __double_as_longlong(t0.x);
            b2[1] = __double_as_longlong(t0.y);
            b2[2] = __double_as_longlong(t1.x);
            b2[3] = __double_as_longlong(t1.y);
            #pragma unroll
            for (int i = 0; i < 8; i++)
                #pragma unroll
                for (int j = 0; j < 4; j++)
                    FMA2(acc2[i][j], ad[i], b2[j]);
        }
        __syncthreads();
    }

    #pragma unroll
    for (int i = 0; i < 8; i++) {
        const int ml = (i < 4) ? (ty * 4 + i) : (64 + ty * 4 + (i - 4));
        const int mm = m0 + ml;
        const float al = bn_g[mm] * rsqrtf(bn_v[mm] + EPSV);
        const float be = bn_b[mm] - bn_m[mm] * al;
        float o[8];
        unpack_f32(acc2[i][0], o[0], o[1]);
        unpack_f32(acc2[i][1], o[2], o[3]);
        unpack_f32(acc2[i][2], o[4], o[5]);
        unpack_f32(acc2[i][3], o[6], o[7]);
        float4 o0, o1;
        o0.x = fmaxf(fmaf(o[0], al, be), 0.f);
        o0.y = fmaxf(fmaf(o[1], al, be), 0.f);
        o0.z = fmaxf(fmaf(o[2], al, be), 0.f);
        o0.w = fmaxf(fmaf(o[3], al, be), 0.f);
        o1.x = fmaxf(fmaf(o[4], al, be), 0.f);
        o1.y = fmaxf(fmaf(o[5], al, be), 0.f);
        o1.z = fmaxf(fmaf(o[6], al, be), 0.f);
        o1.w = fmaxf(fmaf(o[7], al, be), 0.f);
        *(float4*)&zb[(size_t)mm * HW + n0 + tx * 4]      = o0;
        *(float4*)&zb[(size_t)mm * HW + n0 + 64 + tx * 4] = o1;
    }
}

// ---------------- K3: encoding (softmax assign + aggregation), FFMA2 -------
__global__ __launch_bounds__(256) void encode_kernel(
    const float* __restrict__ codewords, const float* __restrict__ scale)
{
    extern __shared__ float sm[];
    float* cwT  = sm;                    // [c][k]  CH*KC = 16384 floats
    float* a_s  = cwT + CH * KC;         // [n][k] stride 33 -> 256*33 = 8448
    float* z_s  = a_s + 256 * 33;        // [64][256] = 16384
    float* sc_s = z_s + 64 * 256;        // 32
    float* c2_s = sc_s + 32;             // 32

    const int tid = threadIdx.x;
    const int b   = blockIdx.y;
    const int n0  = blockIdx.x * 256;
    const float* zb = g_z + (size_t)b * CH * HW;

    for (int i = tid; i < CH * KC; i += 256) {
        int k = i >> 9;
        int c = i & 511;
        cwT[c * KC + k] = codewords[i];
    }
    __syncthreads();
    if (tid < KC) {
        float s = 0.f;
        for (int c = 0; c < CH; c++) { float wv = cwT[c * KC + tid]; s += wv * wv; }
        c2_s[tid] = s;
        sc_s[tid] = scale[tid];
    }
    __syncthreads();

    // ---- pass A: xc, x2, softmax (thread = pixel), packed dual-FMA ----
    const int n = n0 + tid;
    float x2 = 0.f;
    uint64_t xc2[16];
    #pragma unroll
    for (int p = 0; p < 16; p++) xc2[p] = 0ull;
    for (int c = 0; c < CH; c++) {
        float vz = zb[(size_t)c * HW + n];
        x2 = fmaf(vz, vz, x2);
        uint64_t vzd = dup_f32(vz);
        const double2* wp = (const double2*)(cwT + c * KC);   // 8 x double2 = 32 floats
        #pragma unroll
        for (int q = 0; q < 8; q++) {
            double2 wv = wp[q];
            uint64_t w0 = __double_as_longlong(wv.x);
            uint64_t w1 = __double_as_longlong(wv.y);
            FMA2(xc2[2 * q],     vzd, w0);
            FMA2(xc2[2 * q + 1], vzd, w1);
        }
    }
    float xc[KC];
    #pragma unroll
    for (int p = 0; p < 16; p++) unpack_f32(xc2[p], xc[2 * p], xc[2 * p + 1]);

    float mx = -1e30f;
    #pragma unroll
    for (int k = 0; k < KC; k++) {
        float s = sc_s[k] * (x2 - 2.f * xc[k] + c2_s[k]);
        xc[k] = s;
        mx = fmaxf(mx, s);
    }
    float ssum = 0.f;
    #pragma unroll
    for (int k = 0; k < KC; k++) { float e = __expf(xc[k] - mx); xc[k] = e; ssum += e; }
    float inv = 1.f / ssum;
    #pragma unroll
    for (int k = 0; k < KC; k++) a_s[tid * 33 + k] = xc[k] * inv;
    __syncthreads();

    if (tid < KC) {
        float s = 0.f;
        for (int nn = 0; nn < 256; nn++) s += a_s[nn * 33 + tid];
        atomicAdd(&g_asum[b * KC + tid], s);
    }

    // ---- pass B: agg GEMM over c-chunks of 64, packed along nn ----
    const int k  = tid & 31;
    const int cg = tid >> 5;   // warp id 0..7 -> owns 8 channels per chunk
    for (int c0 = 0; c0 < CH; c0 += 64) {
        __syncthreads();
        #pragma unroll
        for (int i = 0; i < 16; i++) {
            int f4  = tid + i * 256;
            int row = f4 >> 6;
            int col = (f4 & 63) * 4;
            *(float4*)&z_s[row * 256 + col] =
                *(const float4*)&zb[(size_t)(c0 + row) * HW + n0 + col];
        }
        __syncthreads();
        uint64_t av2[8];
        #pragma unroll
        for (int j = 0; j < 8; j++) av2[j] = 0ull;
        for (int nn = 0; nn < 256; nn += 2) {
            float a0 = a_s[nn * 33 + k];
            float a1 = a_s[(nn + 1) * 33 + k];
            uint64_t ap = pack_f32(a0, a1);
            #pragma unroll
            for (int j = 0; j < 8; j++) {
                uint64_t zp = __double_as_longlong(
                    *(const double*)&z_s[(cg * 8 + j) * 256 + nn]);  // 8B-aligned, warp broadcast
                FMA2(av2[j], ap, zp);
            }
        }
        #pragma unroll
        for (int j = 0; j < 8; j++) {
            float lo, hi;
            unpack_f32(av2[j], lo, hi);
            atomicAdd(&g_agg[(b * KC + k) * CH + c0 + cg * 8 + j], lo + hi);
        }
    }
}

// ---------------- K4: agg -> BN1 -> ReLU -> mean over codes -> feat ---------
__global__ void finalize_kernel(
    const float* __restrict__ codewords,
    const float* __restrict__ g1, const float* __restrict__ b1,
    const float* __restrict__ m1, const float* __restrict__ v1,
    float* __restrict__ dout)
{
    const int b = blockIdx.y;
    const int c = blockIdx.x * 128 + threadIdx.x;
    float acc = 0.f;
    #pragma unroll
    for (int k = 0; k < KC; k++) {
        float e = g_agg[(b * KC + k) * CH + c] - g_asum[b * KC + k] * codewords[k * CH + c];
        float al = g1[k] * rsqrtf(v1[k] + EPSV);
        e = (e - m1[k]) * al + b1[k];
        acc += fmaxf(e, 0.f);
    }
    float f = acc * (1.f / KC);
    g_feat[b * CH + c] = f;
    dout[b * CH + c] = f;          // output 0: feat [B, C]
}

// ---------------- K5: gamma = sigmoid(feat @ fc_w^T + fc_b) -----------------
// warp-per-output: coalesced fc_w reads + shuffle reduction
__global__ __launch_bounds__(256) void gamma_kernel(
    const float* __restrict__ fc_w, const float* __restrict__ fc_b)
{
    __shared__ float fs[CH];
    const int b = blockIdx.y;
    const int tid = threadIdx.x, wid = tid >> 5, lane = tid & 31;
    fs[tid]       = g_feat[b * CH + tid];
    fs[tid + 256] = g_feat[b * CH + tid + 256];
    __syncthreads();
    const int o = blockIdx.x * 8 + wid;
    float acc = 0.f;
    #pragma unroll
    for (int it = 0; it < 16; it++) {
        int c = it * 32 + lane;
        acc = fmaf(fs[c], fc_w[(size_t)o * CH + c], acc);
    }
    #pragma unroll
    for (int off = 16; off > 0; off >>= 1)
        acc += __shfl_xor_sync(0xFFFFFFFFu, acc, off);
    if (lane == 0)
        g_gamma[b * CH + o] = 1.f / (1.f + expf(-(acc + fc_b[o])));
}

// ---------------- K6: out = relu(x * (1 + gamma)) ---------------------------
__global__ void out_kernel(const float* __restrict__ x, float* __restrict__ dout)
{
    const int i4 = blockIdx.x * blockDim.x + threadIdx.x;  // float4 index
    const int bc = i4 >> 12;                               // (i4*4)/16384
    const float gmm = 1.f + g_gamma[bc];
    float4 v = ((const float4*)x)[i4];
    float4 o;
    o.x = fmaxf(v.x * gmm, 0.f);
    o.y = fmaxf(v.y * gmm, 0.f);
    o.z = fmaxf(v.z * gmm, 0.f);
    o.w = fmaxf(v.w * gmm, 0.f);
    ((float4*)(dout + BATCH * CH))[i4] = o;                // output 1: out [B,C,H,W]
}

// ---------------- launcher --------------------------------------------------
extern "C" void kernel_launch(void* const* d_in, const int* in_sizes, int n_in,
                              void* d_out, int out_size)
{
    const float* x         = (const float*)d_in[0];
    const float* conv_w    = (const float*)d_in[1];
    const float* bn2_g     = (const float*)d_in[2];
    const float* bn2_b     = (const float*)d_in[3];
    const float* bn2_m     = (const float*)d_in[4];
    const float* bn2_v     = (const float*)d_in[5];
    const float* codewords = (const float*)d_in[6];
    const float* scale     = (const float*)d_in[7];
    const float* bn1_g     = (const float*)d_in[8];
    const float* bn1_b     = (const float*)d_in[9];
    const float* bn1_m     = (const float*)d_in[10];
    const float* bn1_v     = (const float*)d_in[11];
    const float* fc_w      = (const float*)d_in[12];
    const float* fc_b      = (const float*)d_in[13];
    float* dout = (float*)d_out;

    const size_t ENC_SMEM = (size_t)(CH * KC + 256 * 33 + 64 * 256 + 64) * sizeof(float);
    cudaFuncSetAttribute(encode_kernel, cudaFuncAttributeMaxDynamicSharedMemorySize,
                         (int)ENC_SMEM);

    gemm_bn_relu<<<dim3(HW / 128, CH / 128, BATCH), 256>>>(
        x, conv_w, bn2_g, bn2_b, bn2_m, bn2_v);
    zero_kernel<<<(BATCH * KC * CH + 255) / 256, 256>>>();
    encode_kernel<<<dim3(HW / 256, BATCH), 256, ENC_SMEM>>>(codewords, scale);
    finalize_kernel<<<dim3(CH / 128, BATCH), 128>>>(
        codewords, bn1_g, bn1_b, bn1_m, bn1_v, dout);
    gamma_kernel<<<dim3(CH / 8, BATCH), 256>>>(fc_w, fc_b);
    out_kernel<<<(BATCH * CH * HW / 4) / 256, 256>>>(x, dout);
}